// round 15
// baseline (speedup 1.0000x reference)
#include <cuda_runtime.h>
#include <math.h>
#include <stdint.h>

#define HQn 16
#define HKn 4
#define Dn 64
#define GATE_CHn 12
#define WINDOWn 1024
#define Bn 2
#define Tn 2048
#define En 1024
#define Fn 1536
#define Mn 4096

// Scratch (allocation-free rule: device globals)
__device__ __align__(256) float g_att[(size_t)Mn * En];
__device__ __align__(256) uint32_t g_qpack[(size_t)Bn * HQn * Tn * Dn];
__device__ __align__(256) uint32_t g_kpack[(size_t)Bn * HKn * Tn * Dn];
__device__ __align__(256) uint32_t g_vpack[(size_t)Bn * HKn * Tn * Dn];

// ---------------------------------------------------------------------------
// helpers
// ---------------------------------------------------------------------------
__device__ __forceinline__ uint32_t f2tf32(float x) {
    uint32_t r;
    asm("cvt.rna.tf32.f32 %0, %1;" : "=r"(r) : "f"(x));
    return r;
}

__device__ __forceinline__ void mma_tf32(float* d, const uint32_t* a,
                                         const uint32_t* b) {
    asm volatile(
        "mma.sync.aligned.m16n8k8.row.col.f32.tf32.tf32.f32 "
        "{%0,%1,%2,%3}, {%4,%5,%6,%7}, {%8,%9}, {%0,%1,%2,%3};\n"
        : "+f"(d[0]), "+f"(d[1]), "+f"(d[2]), "+f"(d[3])
        : "r"(a[0]), "r"(a[1]), "r"(a[2]), "r"(a[3]), "r"(b[0]), "r"(b[1]));
}

__device__ __forceinline__ uint32_t sma(const void* p) {
    return (uint32_t)__cvta_generic_to_shared(p);
}
__device__ __forceinline__ void cp16(uint32_t dst, const void* src) {
    asm volatile("cp.async.cg.shared.global [%0], [%1], 16;\n"
                 :: "r"(dst), "l"(src));
}
__device__ __forceinline__ void cp_commit() {
    asm volatile("cp.async.commit_group;\n");
}
template <int N>
__device__ __forceinline__ void cp_wait() {
    asm volatile("cp.async.wait_group %0;\n" :: "n"(N));
}

__device__ __forceinline__ int permd(int d) {     // 64-chunk k-run permute
    return (d & 3) * 16 + (d >> 2);
}

// ---------------------------------------------------------------------------
// TF32 GEMM (round-12 mainloop): C[M,N] = A[M,K] * B[N,K]^T.
// 128x128 tile, BK=32, 8 warps (32m x 64n), cp.async double-buffered,
// cvt at fragment load, 2 CTAs/SM. FUSED: warp's 64 cols == one head;
// epilogue applies gate/RoPE/RMS and writes attention packs directly.
// ---------------------------------------------------------------------------
#define GBUF_W (128 * 36)
#define GEMM_SMEM_BYTES (4 * GBUF_W * 4)

template <bool FUSED>
__global__ __launch_bounds__(256, 2) void gemm_tf32(
    const float* __restrict__ A, const float* __restrict__ Bm,
    float* __restrict__ C, int M, int N, int K,
    const float* __restrict__ x, const float* __restrict__ ve,
    const float* __restrict__ rc, const float* __restrict__ rs,
    const float* __restrict__ wg, uint32_t* __restrict__ qp,
    uint32_t* __restrict__ kpck, uint32_t* __restrict__ vpck)
{
    extern __shared__ float dynsm[];

    const int tid = threadIdx.x;
    const int lane = tid & 31;
    const int warp = tid >> 5;
    const int wm = (warp & 3) * 32;
    const int wn = (warp >> 2) * 64;
    const int bm = blockIdx.y * 128;
    const int bn = blockIdx.x * 128;
    const int lq = lane >> 2;
    const int lc = lane & 3;

    float acc[2][8][4];
    #pragma unroll
    for (int mt = 0; mt < 2; mt++)
        #pragma unroll
        for (int nt = 0; nt < 8; nt++)
            #pragma unroll
            for (int i = 0; i < 4; i++) acc[mt][nt][i] = 0.f;

    auto pref = [&](int b, int k0) {
        float* Ad = dynsm + b * (2 * GBUF_W);
        float* Bd = Ad + GBUF_W;
        #pragma unroll
        for (int i = 0; i < 4; i++) {
            const int g = tid + 256 * i;
            const int row = g >> 3;
            const int c4 = (g & 7) * 4;
            cp16(sma(Ad + row * 36 + c4), A + (size_t)(bm + row) * K + k0 + c4);
            cp16(sma(Bd + row * 36 + c4), Bm + (size_t)(bn + row) * K + k0 + c4);
        }
    };

    const int niter = K / 32;
    pref(0, 0);
    cp_commit();

    for (int ki = 0; ki < niter; ki++) {
        if (ki + 1 < niter) {
            pref((ki + 1) & 1, (ki + 1) * 32);
            cp_commit();
            cp_wait<1>();
        } else {
            cp_wait<0>();
        }
        __syncthreads();

        const float* Ac = dynsm + (ki & 1) * (2 * GBUF_W);
        const float* Bc = Ac + GBUF_W;

        uint32_t a_all[4][8];
        #pragma unroll
        for (int r = 0; r < 4; r++) {
            const float* p = Ac + (wm + lq + 8 * r) * 36 + lc;
            #pragma unroll
            for (int j = 0; j < 8; j++)
                a_all[r][j] = f2tf32(p[4 * j]);
        }

        #pragma unroll
        for (int g = 0; g < 4; g++) {
            uint32_t bb[2][8];
            #pragma unroll
            for (int j = 0; j < 2; j++) {
                const float* p = Bc + (wn + (g * 2 + j) * 8 + lq) * 36 + lc;
                #pragma unroll
                for (int w = 0; w < 8; w++)
                    bb[j][w] = f2tf32(p[4 * w]);
            }
            #pragma unroll
            for (int ks = 0; ks < 4; ks++) {
                uint32_t af0[4] = {a_all[0][2 * ks], a_all[1][2 * ks],
                                   a_all[0][2 * ks + 1], a_all[1][2 * ks + 1]};
                uint32_t af1[4] = {a_all[2][2 * ks], a_all[3][2 * ks],
                                   a_all[2][2 * ks + 1], a_all[3][2 * ks + 1]};
                #pragma unroll
                for (int j = 0; j < 2; j++) {
                    const int nt = g * 2 + j;
                    uint32_t bf[2] = {bb[j][2 * ks], bb[j][2 * ks + 1]};
                    mma_tf32(acc[0][nt], af0, bf);
                    mma_tf32(acc[1][nt], af1, bf);
                }
            }
        }
        __syncthreads();
    }

    if (!FUSED) {
        #pragma unroll
        for (int mt = 0; mt < 2; mt++) {
            const int r0 = bm + wm + mt * 16 + lq;
            #pragma unroll
            for (int nt = 0; nt < 8; nt++) {
                const int c0 = bn + wn + nt * 8 + 2 * lc;
                *(float2*)(C + (size_t)r0 * N + c0) =
                    make_float2(acc[mt][nt][0], acc[mt][nt][1]);
                *(float2*)(C + (size_t)(r0 + 8) * N + c0) =
                    make_float2(acc[mt][nt][2], acc[mt][nt][3]);
            }
        }
        return;
    }

    // ---- fused epilogue: warp's 64 columns == one head
    const int head = (bn + wn) >> 6;
    if (head < HQn + HKn) {
        #pragma unroll
        for (int mt = 0; mt < 2; mt++) {
            #pragma unroll
            for (int rowh = 0; rowh < 2; rowh++) {
                const int r = bm + wm + mt * 16 + lq + 8 * rowh;
                const int t = r & (Tn - 1);
                const int b = r >> 11;
                float yl[4][2], yh[4][2];
                float ss = 0.f;
                #pragma unroll
                for (int nt = 0; nt < 4; nt++)
                    #pragma unroll
                    for (int e = 0; e < 2; e++) {
                        const int d = nt * 8 + 2 * lc + e;
                        const float cv = rc[t * 32 + d];
                        const float sv = rs[t * 32 + d];
                        const float alo = acc[mt][nt][2 * rowh + e];
                        const float ahi = acc[mt][nt + 4][2 * rowh + e];
                        const float y1 = alo * cv - ahi * sv;
                        const float y2 = alo * sv + ahi * cv;
                        yl[nt][e] = y1; yh[nt][e] = y2;
                        ss += y1 * y1 + y2 * y2;
                    }
                ss += __shfl_xor_sync(0xffffffffu, ss, 1);
                ss += __shfl_xor_sync(0xffffffffu, ss, 2);
                const float rr = rsqrtf(ss * (1.0f / Dn) + 1e-8f);
                if (head < HQn) {
                    uint32_t* q = qp + ((size_t)(b * HQn + head) * Tn + t) * Dn;
                    const float sc = rr * 0.125f;
                    #pragma unroll
                    for (int nt = 0; nt < 4; nt++)
                        #pragma unroll
                        for (int e = 0; e < 2; e++) {
                            const int d = nt * 8 + 2 * lc + e;
                            q[permd(d)]      = f2tf32(yl[nt][e] * sc);
                            q[permd(d + 32)] = f2tf32(yh[nt][e] * sc);
                        }
                } else {
                    const int hk = head - HQn;
                    uint32_t* kd = kpck +
                        ((size_t)(b * HKn + hk) * Tn + t) * Dn;
                    #pragma unroll
                    for (int nt = 0; nt < 4; nt++)
                        #pragma unroll
                        for (int e = 0; e < 2; e++) {
                            const int d = nt * 8 + 2 * lc + e;
                            kd[permd(d)]      = f2tf32(yl[nt][e] * rr);
                            kd[permd(d + 32)] = f2tf32(yh[nt][e] * rr);
                        }
                }
            }
        }
    } else {
        const int hv = head - HQn - HKn;
        #pragma unroll
        for (int mt = 0; mt < 2; mt++) {
            #pragma unroll
            for (int rowh = 0; rowh < 2; rowh++) {
                const int r = bm + wm + mt * 16 + lq + 8 * rowh;
                const int t = r & (Tn - 1);
                const int b = r >> 11;
                float pr = 0.f;
                #pragma unroll
                for (int j = 0; j < 3; j++) {
                    const int c = lc + 4 * j;
                    pr += x[(size_t)r * En + c] * wg[hv * GATE_CHn + c];
                }
                pr += __shfl_xor_sync(0xffffffffu, pr, 1);
                pr += __shfl_xor_sync(0xffffffffu, pr, 2);
                const float gate = 3.0f / (1.0f + __expf(-pr));
                uint32_t* vd = vpck + ((size_t)(b * HKn + hv) * Tn + t) * Dn;
                const float* vep = ve + (size_t)r * (HKn * Dn) + hv * Dn;
                #pragma unroll
                for (int nt = 0; nt < 8; nt++)
                    #pragma unroll
                    for (int e = 0; e < 2; e++) {
                        const int d = nt * 8 + 2 * lc + e;
                        vd[d] = f2tf32(acc[mt][nt][2 * rowh + e]
                                       + gate * vep[d]);
                    }
            }
        }
    }
}

// ---------------------------------------------------------------------------
// Tensor-core flash attention v9: KTILE=64, single-tf32 S (4 acc chains),
// pre-converted operands, cp.async double-buffered, interior-tile mask
// skip, Ps[128][68] permuted (round-7-verified indexing).
// Smem: 2*(64*68 + 64*72) + 128*68 words = 106.5 KB -> 2 CTAs/SM.
// ---------------------------------------------------------------------------
#define QTILE 128
#define KTILE 64
#define AK_W (64 * 68)
#define AV_W (64 * 72)
#define ABUF_W (AK_W + AV_W)
#define W_PS2 (2 * ABUF_W)
#define ATTN_WORDS (W_PS2 + QTILE * 68)
#define ATTN_SMEM_BYTES (ATTN_WORDS * 4)

__global__ __launch_bounds__(256, 2) void attn_tc(
    const uint32_t* __restrict__ qpack, const uint32_t* __restrict__ kpack,
    const uint32_t* __restrict__ vpack, float* __restrict__ out)
{
    extern __shared__ uint32_t smu[];
    uint32_t* Ps = smu + W_PS2;

    const int tid = threadIdx.x;
    const int lane = tid & 31;
    const int warp = tid >> 5;
    const int q0 = blockIdx.x * QTILE;
    const int h  = blockIdx.y;
    const int bb = blockIdx.z;
    const int hk = h >> 2;
    const int row0 = bb * Tn + q0;

    const int lq = lane >> 2;
    const int lc = lane & 3;
    const int rA = warp * 16 + lq;

    const uint32_t* kp_base = kpack + (size_t)(bb * HKn + hk) * Tn * Dn;
    const uint32_t* vp_base = vpack + (size_t)(bb * HKn + hk) * Tn * Dn;

    uint32_t qA[16], qB[16];
    {
        const uint32_t* qp0 = qpack +
            ((size_t)(bb * HQn + h) * Tn + q0 + rA) * Dn + lc * 16;
        const uint32_t* qp1 = qp0 + 8 * Dn;
        #pragma unroll
        for (int u = 0; u < 4; u++) {
            *(uint4*)&qA[4 * u] = *(const uint4*)(qp0 + 4 * u);
            *(uint4*)&qB[4 * u] = *(const uint4*)(qp1 + 4 * u);
        }
    }

    float o[8][4];
    #pragma unroll
    for (int nt = 0; nt < 8; nt++)
        #pragma unroll
        for (int e = 0; e < 4; e++) o[nt][e] = 0.f;
    float lA = 0.f, lB = 0.f;

    const int kt_lo = (q0 > WINDOWn) ? ((q0 - WINDOWn) >> 6) : 0;
    const int kt_hi = (q0 + QTILE - 1) >> 6;

    auto pref = [&](int bidx, int kt) {
        const int kbase = kt * KTILE;
        uint32_t* Kd = smu + bidx * ABUF_W;
        uint32_t* Vd = Kd + AK_W;
        #pragma unroll
        for (int i = 0; i < 8; i++) {
            const int g = tid + 256 * i;
            const int reg = g >> 10;
            const int idx = g & 1023;
            const int row = idx >> 4;
            const int c4 = (idx & 15) * 4;
            if (reg == 0)
                cp16(sma(Kd + row * 68 + c4),
                     kp_base + (size_t)(kbase + row) * Dn + c4);
            else
                cp16(sma(Vd + row * 72 + c4),
                     vp_base + (size_t)(kbase + row) * Dn + c4);
        }
    };

    pref(0, kt_lo);
    cp_commit();

    for (int kt = kt_lo; kt <= kt_hi; kt++) {
        const int cur = (kt - kt_lo) & 1;
        if (kt < kt_hi) {
            pref(cur ^ 1, kt + 1);
            cp_commit();
            cp_wait<1>();
        } else {
            cp_wait<0>();
        }
        __syncthreads();

        const uint32_t* Khi = smu + cur * ABUF_W;
        const uint32_t* Vv  = Khi + AK_W;
        const int k0 = kt * KTILE;
        const bool full_live = (k0 + KTILE - 1 <= q0) &&
                               (k0 >= q0 + QTILE - 1 - WINDOWn);

        #pragma unroll
        for (int nt = 0; nt < 8; nt++) {
            const int key = nt * 8 + lq;
            const uint32_t* ph = Khi + key * 68 + lc * 16;
            uint32_t kh[16];
            #pragma unroll
            for (int u = 0; u < 4; u++)
                *(uint4*)&kh[4 * u] = *(const uint4*)(ph + 4 * u);

            float s0[4] = {0.f, 0.f, 0.f, 0.f};
            float s1[4] = {0.f, 0.f, 0.f, 0.f};
            float s2[4] = {0.f, 0.f, 0.f, 0.f};
            float s3[4] = {0.f, 0.f, 0.f, 0.f};
            #pragma unroll
            for (int kp2 = 0; kp2 < 2; kp2++) {
                const int kb = 4 * kp2;
                #pragma unroll
                for (int c = 0; c < 4; c++) {
                    const int ks = kb + c;
                    uint32_t af[4] = {qA[2 * ks], qB[2 * ks],
                                      qA[2 * ks + 1], qB[2 * ks + 1]};
                    uint32_t bf[2] = {kh[2 * ks], kh[2 * ks + 1]};
                    float* sx = (c == 0) ? s0 : (c == 1) ? s1
                              : (c == 2) ? s2 : s3;
                    mma_tf32(sx, af, bf);
                }
            }

            float p[4];
            if (full_live) {
                #pragma unroll
                for (int e = 0; e < 4; e++)
                    p[e] = __expf(((s0[e] + s1[e]) + (s2[e] + s3[e])) - 8.0f);
            } else {
                #pragma unroll
                for (int e = 0; e < 4; e++) {
                    const float sv = (s0[e] + s1[e]) + (s2[e] + s3[e]);
                    const int i = q0 + rA + ((e >= 2) ? 8 : 0);
                    const int j = k0 + nt * 8 + 2 * lc + (e & 1);
                    const bool live = (j <= i) && (j + WINDOWn >= i);
                    p[e] = live ? __expf(sv - 8.0f) : 0.f;
                }
            }
            lA += p[0] + p[1];
            lB += p[2] + p[3];

            #pragma unroll
            for (int e = 0; e < 4; e++) {
                const int col = nt * 8 + 2 * lc + (e & 1);
                const int pc = ((col & 3) << 4) | (col >> 2);
                const int row = rA + ((e >= 2) ? 8 : 0);
                Ps[row * 68 + (pc ^ (((row >> 3) & 3) << 4))] = f2tf32(p[e]);
            }
        }
        __syncwarp();   // own-warp P rows only

        uint32_t pA[16], pB[16];
        {
            const uint32_t* p0 = &Ps[rA * 68 + ((lc ^ ((rA >> 3) & 3)) << 4)];
            const int rB = rA + 8;
            const uint32_t* p1 = &Ps[rB * 68 + ((lc ^ ((rB >> 3) & 3)) << 4)];
            #pragma unroll
            for (int u = 0; u < 4; u++) {
                *(uint4*)&pA[4 * u] = *(const uint4*)(p0 + 4 * u);
                *(uint4*)&pB[4 * u] = *(const uint4*)(p1 + 4 * u);
            }
        }
        #pragma unroll
        for (int ks = 0; ks < 8; ks++) {
            const int kp = ks * 8 + lc;
            uint32_t af[4] = {pA[2 * ks], pB[2 * ks],
                              pA[2 * ks + 1], pB[2 * ks + 1]};
            #pragma unroll
            for (int nt = 0; nt < 8; nt++) {
                const int d = nt * 8 + lq;
                uint32_t bf[2] = {Vv[kp * 72 + d], Vv[(kp + 4) * 72 + d]};
                mma_tf32(o[nt], af, bf);
            }
        }
        __syncthreads();   // cur fully consumed before next pref overwrites
    }

    lA += __shfl_xor_sync(0xffffffffu, lA, 1);
    lA += __shfl_xor_sync(0xffffffffu, lA, 2);
    lB += __shfl_xor_sync(0xffffffffu, lB, 1);
    lB += __shfl_xor_sync(0xffffffffu, lB, 2);
    const float invA = 1.0f / lA;
    const float invB = 1.0f / lB;

    #pragma unroll
    for (int nt = 0; nt < 8; nt++) {
        const int c0 = h * Dn + nt * 8 + 2 * lc;
        *(float2*)(out + (size_t)(row0 + rA) * En + c0) =
            make_float2(o[nt][0] * invA, o[nt][1] * invA);
        *(float2*)(out + (size_t)(row0 + rA + 8) * En + c0) =
            make_float2(o[nt][2] * invB, o[nt][3] * invB);
    }
}

// ---------------------------------------------------------------------------
extern "C" void kernel_launch(void* const* d_in, const int* in_sizes, int n_in,
                              void* d_out, int out_size)
{
    (void)in_sizes; (void)n_in; (void)out_size;
    const float* x    = (const float*)d_in[0];
    const float* ve   = (const float*)d_in[1];
    const float* rc   = (const float*)d_in[2];
    const float* rs   = (const float*)d_in[3];
    const float* wqkv = (const float*)d_in[4];
    const float* wg   = (const float*)d_in[5];
    const float* wo   = (const float*)d_in[6];
    float* out = (float*)d_out;

    float* att_p = nullptr;
    uint32_t *qp = nullptr, *kp = nullptr, *vp = nullptr;
    cudaGetSymbolAddress((void**)&att_p, g_att);
    cudaGetSymbolAddress((void**)&qp, g_qpack);
    cudaGetSymbolAddress((void**)&kp, g_kpack);
    cudaGetSymbolAddress((void**)&vp, g_vpack);

    cudaFuncSetAttribute(gemm_tf32<true>,
                         cudaFuncAttributeMaxDynamicSharedMemorySize,
                         GEMM_SMEM_BYTES);
    cudaFuncSetAttribute(gemm_tf32<false>,
                         cudaFuncAttributeMaxDynamicSharedMemorySize,
                         GEMM_SMEM_BYTES);
    cudaFuncSetAttribute(attn_tc,
                         cudaFuncAttributeMaxDynamicSharedMemorySize,
                         ATTN_SMEM_BYTES);

    gemm_tf32<true><<<dim3(Fn / 128, Mn / 128), 256, GEMM_SMEM_BYTES>>>(
        x, wqkv, nullptr, Mn, Fn, En, x, ve, rc, rs, wg, qp, kp, vp);
    attn_tc<<<dim3(Tn / QTILE, HQn, Bn), 256, ATTN_SMEM_BYTES>>>(
        qp, kp, vp, att_p);
    gemm_tf32<false><<<dim3(En / 128, Mn / 128), 256, GEMM_SMEM_BYTES>>>(
        att_p, wo, out, Mn, En, En,
        nullptr, nullptr, nullptr, nullptr, nullptr, nullptr, nullptr, nullptr);
}

// round 16
// speedup vs baseline: 1.7693x; 1.7693x over previous
#include <cuda_runtime.h>
#include <cuda_fp16.h>
#include <math.h>
#include <stdint.h>

#define HQn 16
#define HKn 4
#define Dn 64
#define GATE_CHn 12
#define WINDOWn 1024
#define Bn 2
#define Tn 2048
#define En 1024
#define Fn 1536
#define Mn 4096

// Scratch (allocation-free rule: device globals). All fp16 data stored as
// uint32_t words (half2 pairs).
__device__ __align__(256) uint32_t g_att[(size_t)Mn * En / 2];
__device__ __align__(256) uint32_t g_xh[(size_t)Mn * En / 2];
__device__ __align__(256) uint32_t g_wqh[(size_t)Fn * En / 2];
__device__ __align__(256) uint32_t g_woh[(size_t)En * En / 2];
__device__ __align__(256) uint32_t g_qpack[(size_t)Bn * HQn * Tn * 32];
__device__ __align__(256) uint32_t g_kpack[(size_t)Bn * HKn * Tn * 32];
__device__ __align__(256) uint32_t g_vpack[(size_t)Bn * HKn * Dn * Tn / 2]; // [b][hk][d][t/2]

// ---------------------------------------------------------------------------
// helpers
// ---------------------------------------------------------------------------
__device__ __forceinline__ uint32_t pack2(float lo, float hi) {
    __half2 h = __floats2half2_rn(lo, hi);
    return *(uint32_t*)&h;
}

__device__ __forceinline__ void mma_f16(float* d, const uint32_t* a,
                                        const uint32_t* b) {
    asm volatile(
        "mma.sync.aligned.m16n8k16.row.col.f32.f16.f16.f32 "
        "{%0,%1,%2,%3}, {%4,%5,%6,%7}, {%8,%9}, {%0,%1,%2,%3};\n"
        : "+f"(d[0]), "+f"(d[1]), "+f"(d[2]), "+f"(d[3])
        : "r"(a[0]), "r"(a[1]), "r"(a[2]), "r"(a[3]), "r"(b[0]), "r"(b[1]));
}

__device__ __forceinline__ uint32_t sma(const void* p) {
    return (uint32_t)__cvta_generic_to_shared(p);
}
__device__ __forceinline__ void cp16(uint32_t dst, const void* src) {
    asm volatile("cp.async.cg.shared.global [%0], [%1], 16;\n"
                 :: "r"(dst), "l"(src));
}
__device__ __forceinline__ void cp_commit() {
    asm volatile("cp.async.commit_group;\n");
}
template <int N>
__device__ __forceinline__ void cp_wait() {
    asm volatile("cp.async.wait_group %0;\n" :: "n"(N));
}

// ---------------------------------------------------------------------------
// Prepass: fp32 -> fp16 (rn), packed half2 words, canonical order.
// ---------------------------------------------------------------------------
__global__ void cvt_h(const float* __restrict__ src,
                      uint32_t* __restrict__ dst, int n4)
{
    const int i = blockIdx.x * blockDim.x + threadIdx.x;
    if (i < n4) {
        float4 v = ((const float4*)src)[i];
        uint2 o;
        o.x = pack2(v.x, v.y);
        o.y = pack2(v.z, v.w);
        ((uint2*)dst)[i] = o;
    }
}

// ---------------------------------------------------------------------------
// FP16 GEMM: C[M,N] = A[M,K] * B[N,K]^T (fp16 half2-word inputs).
// 128x128 tile, BK=32 (2 x m16n8k16 k-chunks), 8 warps (32m x 64n),
// cp.async double-buffered, smem row stride 20 words (16 + pad, fragment
// scalar LDS conflict-free), 2 CTAs/SM.
// FUSED: each warp's 64 cols == one head; epilogue applies gate/RoPE/RMS
// and writes fp16 attention packs directly.
// ---------------------------------------------------------------------------
#define GW 20
#define GA_W (128 * GW)
#define GSTG_W (2 * GA_W)
#define GEMM_SMEM_BYTES (2 * GSTG_W * 4)

template <bool FUSED>
__global__ __launch_bounds__(256, 2) void gemm_f16(
    const uint32_t* __restrict__ A, const uint32_t* __restrict__ Bm,
    float* __restrict__ C, int M, int N, int K,
    const float* __restrict__ x, const float* __restrict__ ve,
    const float* __restrict__ rc, const float* __restrict__ rs,
    const float* __restrict__ wg, uint32_t* __restrict__ qp,
    uint32_t* __restrict__ kpck, uint32_t* __restrict__ vpck)
{
    extern __shared__ uint32_t gsm[];

    const int tid = threadIdx.x;
    const int lane = tid & 31;
    const int warp = tid >> 5;
    const int wm = (warp & 3) * 32;
    const int wn = (warp >> 2) * 64;
    const int bm = blockIdx.y * 128;
    const int bn = blockIdx.x * 128;
    const int lq = lane >> 2;
    const int lc = lane & 3;
    const int Kw = K >> 1;           // words per gmem row

    float acc[2][8][4];
    #pragma unroll
    for (int mt = 0; mt < 2; mt++)
        #pragma unroll
        for (int nt = 0; nt < 8; nt++)
            #pragma unroll
            for (int i = 0; i < 4; i++) acc[mt][nt][i] = 0.f;

    auto pref = [&](int b, int kc) {       // kc = BK-chunk index
        uint32_t* Ad = gsm + b * GSTG_W;
        uint32_t* Bd = Ad + GA_W;
        const int k0w = kc * 16;
        #pragma unroll
        for (int i = 0; i < 2; i++) {
            const int g = tid + 256 * i;
            const int row = g >> 2;
            const int c4 = (g & 3) * 4;
            cp16(sma(Ad + row * GW + c4), A + (size_t)(bm + row) * Kw + k0w + c4);
            cp16(sma(Bd + row * GW + c4), Bm + (size_t)(bn + row) * Kw + k0w + c4);
        }
    };

    const int niter = K / 32;
    pref(0, 0);
    cp_commit();

    for (int ki = 0; ki < niter; ki++) {
        if (ki + 1 < niter) {
            pref((ki + 1) & 1, ki + 1);
            cp_commit();
            cp_wait<1>();
        } else {
            cp_wait<0>();
        }
        __syncthreads();

        const uint32_t* Ac = gsm + (ki & 1) * GSTG_W;
        const uint32_t* Bc = Ac + GA_W;

        // A fragments: [mt][chunk][4] (rows lq, lq+8 of each m16 tile)
        uint32_t af[2][2][4];
        #pragma unroll
        for (int mt = 0; mt < 2; mt++) {
            const uint32_t* p0 = Ac + (wm + mt * 16 + lq) * GW;
            const uint32_t* p1 = p0 + 8 * GW;
            #pragma unroll
            for (int c = 0; c < 2; c++) {
                af[mt][c][0] = p0[8 * c + lc];
                af[mt][c][1] = p1[8 * c + lc];
                af[mt][c][2] = p0[8 * c + lc + 4];
                af[mt][c][3] = p1[8 * c + lc + 4];
            }
        }

        #pragma unroll
        for (int nt = 0; nt < 8; nt++) {
            const uint32_t* pb = Bc + (wn + nt * 8 + lq) * GW;
            uint32_t b0[2] = {pb[lc], pb[lc + 4]};
            uint32_t b1[2] = {pb[8 + lc], pb[8 + lc + 4]};
            mma_f16(acc[0][nt], af[0][0], b0);
            mma_f16(acc[1][nt], af[1][0], b0);
            mma_f16(acc[0][nt], af[0][1], b1);
            mma_f16(acc[1][nt], af[1][1], b1);
        }
        __syncthreads();
    }

    if (!FUSED) {
        #pragma unroll
        for (int mt = 0; mt < 2; mt++) {
            const int r0 = bm + wm + mt * 16 + lq;
            #pragma unroll
            for (int nt = 0; nt < 8; nt++) {
                const int c0 = bn + wn + nt * 8 + 2 * lc;
                *(float2*)(C + (size_t)r0 * N + c0) =
                    make_float2(acc[mt][nt][0], acc[mt][nt][1]);
                *(float2*)(C + (size_t)(r0 + 8) * N + c0) =
                    make_float2(acc[mt][nt][2], acc[mt][nt][3]);
            }
        }
        return;
    }

    // ---- fused epilogue: warp's 64 columns == one head
    const int head = (bn + wn) >> 6;
    if (head < HQn + HKn) {
        #pragma unroll
        for (int mt = 0; mt < 2; mt++) {
            #pragma unroll
            for (int rowh = 0; rowh < 2; rowh++) {
                const int r = bm + wm + mt * 16 + lq + 8 * rowh;
                const int t = r & (Tn - 1);
                const int b = r >> 11;
                float yl[4][2], yh[4][2];
                float ss = 0.f;
                #pragma unroll
                for (int nt = 0; nt < 4; nt++)
                    #pragma unroll
                    for (int e = 0; e < 2; e++) {
                        const int d = nt * 8 + 2 * lc + e;
                        const float cv = rc[t * 32 + d];
                        const float sv = rs[t * 32 + d];
                        const float alo = acc[mt][nt][2 * rowh + e];
                        const float ahi = acc[mt][nt + 4][2 * rowh + e];
                        const float y1 = alo * cv - ahi * sv;
                        const float y2 = alo * sv + ahi * cv;
                        yl[nt][e] = y1; yh[nt][e] = y2;
                        ss += y1 * y1 + y2 * y2;
                    }
                ss += __shfl_xor_sync(0xffffffffu, ss, 1);
                ss += __shfl_xor_sync(0xffffffffu, ss, 2);
                const float rr = rsqrtf(ss * (1.0f / Dn) + 1e-8f);
                if (head < HQn) {
                    uint32_t* qw = qp + ((size_t)(b * HQn + head) * Tn + t) * 32;
                    const float sc = rr * 0.125f;
                    #pragma unroll
                    for (int nt = 0; nt < 4; nt++) {
                        qw[nt * 4 + lc] =
                            pack2(yl[nt][0] * sc, yl[nt][1] * sc);
                        qw[16 + nt * 4 + lc] =
                            pack2(yh[nt][0] * sc, yh[nt][1] * sc);
                    }
                } else {
                    const int hk = head - HQn;
                    uint32_t* kw = kpck +
                        ((size_t)(b * HKn + hk) * Tn + t) * 32;
                    #pragma unroll
                    for (int nt = 0; nt < 4; nt++) {
                        kw[nt * 4 + lc] =
                            pack2(yl[nt][0] * rr, yl[nt][1] * rr);
                        kw[16 + nt * 4 + lc] =
                            pack2(yh[nt][0] * rr, yh[nt][1] * rr);
                    }
                }
            }
        }
    } else {
        // v head: gate mix + transposed fp16 pack ([d][t])
        const int hv = head - HQn - HKn;
        #pragma unroll
        for (int mt = 0; mt < 2; mt++) {
            #pragma unroll
            for (int rowh = 0; rowh < 2; rowh++) {
                const int r = bm + wm + mt * 16 + lq + 8 * rowh;
                const int t = r & (Tn - 1);
                const int b = r >> 11;
                float pr = 0.f;
                #pragma unroll
                for (int j = 0; j < 3; j++) {
                    const int c = lc + 4 * j;
                    pr += x[(size_t)r * En + c] * wg[hv * GATE_CHn + c];
                }
                pr += __shfl_xor_sync(0xffffffffu, pr, 1);
                pr += __shfl_xor_sync(0xffffffffu, pr, 2);
                const float gate = 3.0f / (1.0f + __expf(-pr));
                __half* vh = (__half*)(vpck +
                    (size_t)(b * HKn + hv) * Dn * (Tn / 2));
                const float* vep = ve + (size_t)r * (HKn * Dn) + hv * Dn;
                #pragma unroll
                for (int nt = 0; nt < 8; nt++)
                    #pragma unroll
                    for (int e = 0; e < 2; e++) {
                        const int d = nt * 8 + 2 * lc + e;
                        vh[(size_t)d * Tn + t] = __float2half(
                            acc[mt][nt][2 * rowh + e] + gate * vep[d]);
                    }
            }
        }
    }
}

// ---------------------------------------------------------------------------
// FP16 tensor-core flash attention: m16n8k16, KTILE=64, cp.async double-
// buffered K (rows [64][36w]) and V-transposed (rows d [64][36w]),
// fixed-max softmax, Ps half2 [128][36w], interior-tile mask skip.
// Output fp16 packed (consumed by gemm_f16<false>).
// ---------------------------------------------------------------------------
#define KT 64
#define KWs 36
#define AKW (64 * KWs)
#define ABW (2 * AKW)
#define W_PSa (2 * ABW)
#define ATTN_WORDS (W_PSa + 128 * 36)
#define ATTN_SMEM_BYTES (ATTN_WORDS * 4)

__global__ __launch_bounds__(256, 2) void attn_f16(
    const uint32_t* __restrict__ qpack, const uint32_t* __restrict__ kpack,
    const uint32_t* __restrict__ vpack, uint32_t* __restrict__ outw)
{
    extern __shared__ uint32_t smu[];
    uint32_t* Ps = smu + W_PSa;

    const int tid = threadIdx.x;
    const int lane = tid & 31;
    const int warp = tid >> 5;
    const int q0 = blockIdx.x * 128;
    const int h  = blockIdx.y;
    const int bb = blockIdx.z;
    const int hk = h >> 2;
    const int row0 = bb * Tn + q0;

    const int lq = lane >> 2;
    const int lc = lane & 3;
    const int rA = warp * 16 + lq;

    const uint32_t* kpb = kpack + (size_t)(bb * HKn + hk) * Tn * 32;
    const uint32_t* vpb = vpack + (size_t)(bb * HKn + hk) * Dn * (Tn / 2);

    // Q fragments (fp16, pre-scaled by 1/8): [chunk][4]
    uint32_t qf[4][4];
    {
        const uint32_t* q0p = qpack +
            ((size_t)(bb * HQn + h) * Tn + q0 + rA) * 32;
        const uint32_t* q1p = q0p + 8 * 32;
        #pragma unroll
        for (int c = 0; c < 4; c++) {
            qf[c][0] = q0p[8 * c + lc];
            qf[c][1] = q1p[8 * c + lc];
            qf[c][2] = q0p[8 * c + lc + 4];
            qf[c][3] = q1p[8 * c + lc + 4];
        }
    }

    float o[8][4];
    #pragma unroll
    for (int nt = 0; nt < 8; nt++)
        #pragma unroll
        for (int e = 0; e < 4; e++) o[nt][e] = 0.f;
    float lA = 0.f, lB = 0.f;

    const int kt_lo = (q0 > WINDOWn) ? ((q0 - WINDOWn) >> 6) : 0;
    const int kt_hi = (q0 + 127) >> 6;

    auto pref = [&](int bidx, int kt) {
        uint32_t* Kd = smu + bidx * ABW;
        uint32_t* Vd = Kd + AKW;
        #pragma unroll
        for (int i = 0; i < 4; i++) {
            const int g = tid + 256 * i;
            const int reg = g >> 9;
            const int idx = g & 511;
            const int row = idx >> 3;
            const int c4 = (idx & 7) * 4;
            if (reg == 0)
                cp16(sma(Kd + row * KWs + c4),
                     kpb + (size_t)(kt * 64 + row) * 32 + c4);
            else
                cp16(sma(Vd + row * KWs + c4),
                     vpb + (size_t)row * (Tn / 2) + kt * 32 + c4);
        }
    };

    pref(0, kt_lo);
    cp_commit();

    for (int kt = kt_lo; kt <= kt_hi; kt++) {
        const int cur = (kt - kt_lo) & 1;
        if (kt < kt_hi) {
            pref(cur ^ 1, kt + 1);
            cp_commit();
            cp_wait<1>();
        } else {
            cp_wait<0>();
        }
        __syncthreads();

        const uint32_t* Kc = smu + cur * ABW;
        const uint32_t* Vc = Kc + AKW;
        const int k0 = kt * KT;
        const bool full_live = (k0 + KT - 1 <= q0) &&
                               (k0 >= q0 + 127 - WINDOWn);

        // ---- S = Q K^T + softmax + P store
        #pragma unroll
        for (int nt = 0; nt < 8; nt++) {
            const uint32_t* kw = Kc + (nt * 8 + lq) * KWs;
            float s0[4] = {0.f, 0.f, 0.f, 0.f};
            float s1[4] = {0.f, 0.f, 0.f, 0.f};
            #pragma unroll
            for (int c = 0; c < 4; c++) {
                uint32_t bf[2] = {kw[8 * c + lc], kw[8 * c + lc + 4]};
                mma_f16((c & 1) ? s1 : s0, qf[c], bf);
            }

            float p[4];
            if (full_live) {
                #pragma unroll
                for (int e = 0; e < 4; e++)
                    p[e] = __expf((s0[e] + s1[e]) - 8.0f);
            } else {
                #pragma unroll
                for (int e = 0; e < 4; e++) {
                    const float sv = s0[e] + s1[e];
                    const int i = q0 + rA + ((e >= 2) ? 8 : 0);
                    const int j = k0 + nt * 8 + 2 * lc + (e & 1);
                    const bool live = (j <= i) && (j + WINDOWn >= i);
                    p[e] = live ? __expf(sv - 8.0f) : 0.f;
                }
            }
            lA += p[0] + p[1];
            lB += p[2] + p[3];

            Ps[rA * 36 + nt * 4 + lc] = pack2(p[0], p[1]);
            Ps[(rA + 8) * 36 + nt * 4 + lc] = pack2(p[2], p[3]);
        }
        __syncwarp();   // own-warp P rows only

        // ---- O += P V  (c-outer for o reuse distance 8)
        uint32_t pa[4][4];
        {
            const uint32_t* p0 = Ps + rA * 36;
            const uint32_t* p1 = Ps + (rA + 8) * 36;
            #pragma unroll
            for (int c = 0; c < 4; c++) {
                pa[c][0] = p0[8 * c + lc];
                pa[c][1] = p1[8 * c + lc];
                pa[c][2] = p0[8 * c + lc + 4];
                pa[c][3] = p1[8 * c + lc + 4];
            }
        }
        #pragma unroll
        for (int c = 0; c < 4; c++) {
            #pragma unroll
            for (int nt = 0; nt < 8; nt++) {
                const uint32_t* vw = Vc + (nt * 8 + lq) * KWs;
                uint32_t bf[2] = {vw[8 * c + lc], vw[8 * c + lc + 4]};
                mma_f16(o[nt], pa[c], bf);
            }
        }
        __syncthreads();   // cur fully consumed before next pref overwrites
    }

    lA += __shfl_xor_sync(0xffffffffu, lA, 1);
    lA += __shfl_xor_sync(0xffffffffu, lA, 2);
    lB += __shfl_xor_sync(0xffffffffu, lB, 1);
    lB += __shfl_xor_sync(0xffffffffu, lB, 2);
    const float invA = 1.0f / lA;
    const float invB = 1.0f / lB;

    // fp16 packed output (row stride En/2 words)
    #pragma unroll
    for (int nt = 0; nt < 8; nt++) {
        const int cw = h * 32 + nt * 4 + lc;
        outw[(size_t)(row0 + rA) * (En / 2) + cw] =
            pack2(o[nt][0] * invA, o[nt][1] * invA);
        outw[(size_t)(row0 + rA + 8) * (En / 2) + cw] =
            pack2(o[nt][2] * invB, o[nt][3] * invB);
    }
}

// ---------------------------------------------------------------------------
extern "C" void kernel_launch(void* const* d_in, const int* in_sizes, int n_in,
                              void* d_out, int out_size)
{
    (void)in_sizes; (void)n_in; (void)out_size;
    const float* x    = (const float*)d_in[0];
    const float* ve   = (const float*)d_in[1];
    const float* rc   = (const float*)d_in[2];
    const float* rs   = (const float*)d_in[3];
    const float* wqkv = (const float*)d_in[4];
    const float* wg   = (const float*)d_in[5];
    const float* wo   = (const float*)d_in[6];
    float* out = (float*)d_out;

    uint32_t *att_p, *qp, *kp, *vp, *xh, *wqh, *woh;
    cudaGetSymbolAddress((void**)&att_p, g_att);
    cudaGetSymbolAddress((void**)&qp, g_qpack);
    cudaGetSymbolAddress((void**)&kp, g_kpack);
    cudaGetSymbolAddress((void**)&vp, g_vpack);
    cudaGetSymbolAddress((void**)&xh, g_xh);
    cudaGetSymbolAddress((void**)&wqh, g_wqh);
    cudaGetSymbolAddress((void**)&woh, g_woh);

    cudaFuncSetAttribute(gemm_f16<true>,
                         cudaFuncAttributeMaxDynamicSharedMemorySize,
                         GEMM_SMEM_BYTES);
    cudaFuncSetAttribute(gemm_f16<false>,
                         cudaFuncAttributeMaxDynamicSharedMemorySize,
                         GEMM_SMEM_BYTES);
    cudaFuncSetAttribute(attn_f16,
                         cudaFuncAttributeMaxDynamicSharedMemorySize,
                         ATTN_SMEM_BYTES);

    cvt_h<<<(Mn * En / 4 + 255) / 256, 256>>>(x, xh, Mn * En / 4);
    cvt_h<<<(Fn * En / 4 + 255) / 256, 256>>>(wqkv, wqh, Fn * En / 4);
    cvt_h<<<(En * En / 4 + 255) / 256, 256>>>(wo, woh, En * En / 4);

    // qkv projection with fused gate/RoPE/RMS/pack epilogue
    gemm_f16<true><<<dim3(Fn / 128, Mn / 128), 256, GEMM_SMEM_BYTES>>>(
        xh, wqh, nullptr, Mn, Fn, En, x, ve, rc, rs, wg, qp, kp, vp);
    attn_f16<<<dim3(Tn / 128, HQn, Bn), 256, ATTN_SMEM_BYTES>>>(
        qp, kp, vp, att_p);
    gemm_f16<false><<<dim3(En / 128, Mn / 128), 256, GEMM_SMEM_BYTES>>>(
        att_p, woh, out, Mn, En, En,
        nullptr, nullptr, nullptr, nullptr, nullptr, nullptr, nullptr, nullptr);
}